// round 2
// baseline (speedup 1.0000x reference)
#include <cuda_runtime.h>
#include <cuda_bf16.h>
#include <math.h>

// Problem constants (fixed by reference setup_inputs)
#define B_ROWS 16384
#define D_DIM  3072
#define NQ     4
#define NC     3

#define THREADS 256
#define WARPS_PER_BLOCK 8
#define ROWS_PER_WARP 4
#define ROWS_PER_BLOCK (WARPS_PER_BLOCK * ROWS_PER_WARP)   // 32
#define GRID (B_ROWS / ROWS_PER_BLOCK)                      // 512

__global__ __launch_bounds__(THREADS)
void qnet_fused_kernel(const float* __restrict__ x,
                       const float* __restrict__ pre_w,
                       const float* __restrict__ pre_b,
                       const float* __restrict__ q_params,
                       const float* __restrict__ post_w,
                       const float* __restrict__ post_b,
                       float* __restrict__ out)
{
    // Stage pre_w [4][3072] in shared: 48 KB exactly (static smem limit).
    __shared__ float sw[NQ * D_DIM];
    {
        const float4* src = reinterpret_cast<const float4*>(pre_w);
        float4* dst = reinterpret_cast<float4*>(sw);
        #pragma unroll
        for (int i = threadIdx.x; i < NQ * D_DIM / 4; i += THREADS)
            dst[i] = src[i];
    }
    __syncthreads();

    const int warp = threadIdx.x >> 5;
    const int lane = threadIdx.x & 31;
    const int row0 = (blockIdx.x * WARPS_PER_BLOCK + warp) * ROWS_PER_WARP;

    const float4* xb = reinterpret_cast<const float4*>(x);
    const float4* xr0 = xb + (size_t)(row0 + 0) * (D_DIM / 4);
    const float4* xr1 = xb + (size_t)(row0 + 1) * (D_DIM / 4);
    const float4* xr2 = xb + (size_t)(row0 + 2) * (D_DIM / 4);
    const float4* xr3 = xb + (size_t)(row0 + 3) * (D_DIM / 4);
    const float4* sw4 = reinterpret_cast<const float4*>(sw);

    // acc[r][q] : partial dot of row (row0+r) with weight row q, over this lane's columns
    float acc[ROWS_PER_WARP][NQ];
    #pragma unroll
    for (int r = 0; r < ROWS_PER_WARP; ++r)
        #pragma unroll
        for (int q = 0; q < NQ; ++q) acc[r][q] = 0.0f;

    // Lanes sweep D in float4: per iter a warp covers 128 columns.
    #pragma unroll 2
    for (int it = 0; it < D_DIM / 128; ++it) {
        const int c4 = it * 32 + lane;  // float4 column index
        float4 w0 = sw4[0 * (D_DIM / 4) + c4];
        float4 w1 = sw4[1 * (D_DIM / 4) + c4];
        float4 w2 = sw4[2 * (D_DIM / 4) + c4];
        float4 w3 = sw4[3 * (D_DIM / 4) + c4];

        float4 xv;
        xv = xr0[c4];
        acc[0][0] += xv.x*w0.x + xv.y*w0.y + xv.z*w0.z + xv.w*w0.w;
        acc[0][1] += xv.x*w1.x + xv.y*w1.y + xv.z*w1.z + xv.w*w1.w;
        acc[0][2] += xv.x*w2.x + xv.y*w2.y + xv.z*w2.z + xv.w*w2.w;
        acc[0][3] += xv.x*w3.x + xv.y*w3.y + xv.z*w3.z + xv.w*w3.w;
        xv = xr1[c4];
        acc[1][0] += xv.x*w0.x + xv.y*w0.y + xv.z*w0.z + xv.w*w0.w;
        acc[1][1] += xv.x*w1.x + xv.y*w1.y + xv.z*w1.z + xv.w*w1.w;
        acc[1][2] += xv.x*w2.x + xv.y*w2.y + xv.z*w2.z + xv.w*w2.w;
        acc[1][3] += xv.x*w3.x + xv.y*w3.y + xv.z*w3.z + xv.w*w3.w;
        xv = xr2[c4];
        acc[2][0] += xv.x*w0.x + xv.y*w0.y + xv.z*w0.z + xv.w*w0.w;
        acc[2][1] += xv.x*w1.x + xv.y*w1.y + xv.z*w1.z + xv.w*w1.w;
        acc[2][2] += xv.x*w2.x + xv.y*w2.y + xv.z*w2.z + xv.w*w2.w;
        acc[2][3] += xv.x*w3.x + xv.y*w3.y + xv.z*w3.z + xv.w*w3.w;
        xv = xr3[c4];
        acc[3][0] += xv.x*w0.x + xv.y*w0.y + xv.z*w0.z + xv.w*w0.w;
        acc[3][1] += xv.x*w1.x + xv.y*w1.y + xv.z*w1.z + xv.w*w1.w;
        acc[3][2] += xv.x*w2.x + xv.y*w2.y + xv.z*w2.z + xv.w*w2.w;
        acc[3][3] += xv.x*w3.x + xv.y*w3.y + xv.z*w3.z + xv.w*w3.w;
    }

    // Butterfly reduce each of the 16 accumulators across the warp.
    #pragma unroll
    for (int r = 0; r < ROWS_PER_WARP; ++r)
        #pragma unroll
        for (int q = 0; q < NQ; ++q) {
            float v = acc[r][q];
            v += __shfl_xor_sync(0xFFFFFFFFu, v, 16);
            v += __shfl_xor_sync(0xFFFFFFFFu, v, 8);
            v += __shfl_xor_sync(0xFFFFFFFFu, v, 4);
            v += __shfl_xor_sync(0xFFFFFFFFu, v, 2);
            v += __shfl_xor_sync(0xFFFFFFFFu, v, 1);
            acc[r][q] = v;
        }

    // Lanes 0..3 each handle one row: tanh encode -> 4-qubit real statevector
    // sim -> <Z_w> -> post linear. All register-resident, fully unrolled.
    if (lane < ROWS_PER_WARP) {
        const int row = row0 + lane;

        // select acc[lane][*] with static indices (avoid dynamic reg indexing)
        float dot[NQ];
        #pragma unroll
        for (int q = 0; q < NQ; ++q) {
            float v = acc[0][q];
            if (lane == 1) v = acc[1][q];
            if (lane == 2) v = acc[2][q];
            if (lane == 3) v = acc[3][q];
            dot[q] = v;
        }

        const float PI_3 = 1.0471975511965976f;  // pi/3
        float cs[NQ], sn[NQ];
        #pragma unroll
        for (int q = 0; q < NQ; ++q) {
            float h = tanhf(dot[q] + pre_b[q]) * PI_3;
            sincosf(0.5f * h, &sn[q], &cs[q]);
        }

        // Initial state after per-qubit RY encodings on |0>^4: product state,
        // bit w of index i selects sin vs cos. State is purely real.
        float st[16];
        #pragma unroll
        for (int i = 0; i < 16; ++i) {
            float v = (i & 1) ? sn[0] : cs[0];
            v *= (i & 2) ? sn[1] : cs[1];
            v *= (i & 4) ? sn[2] : cs[2];
            v *= (i & 8) ? sn[3] : cs[3];
            st[i] = v;
        }

        // 3 layers: RY(q_params[8l+w]) on w=0..3, then CNOT(w,(w+1)%4) w=0..3
        #pragma unroll
        for (int l = 0; l < 3; ++l) {
            #pragma unroll
            for (int w = 0; w < 4; ++w) {
                const float th = q_params[l * 8 + w];
                float gs, gc;
                sincosf(0.5f * th, &gs, &gc);
                const int m = 1 << w;
                #pragma unroll
                for (int i = 0; i < 16; ++i) {
                    if (!(i & m)) {
                        const int j = i | m;
                        const float a0 = st[i], a1 = st[j];
                        st[i] = gc * a0 - gs * a1;
                        st[j] = gs * a0 + gc * a1;
                    }
                }
            }
            #pragma unroll
            for (int w = 0; w < 4; ++w) {
                const int cm = 1 << w;
                const int tm = 1 << ((w + 1) & 3);
                #pragma unroll
                for (int i = 0; i < 16; ++i) {
                    if ((i & cm) && !(i & tm)) {
                        const int j = i | tm;
                        const float t = st[i]; st[i] = st[j]; st[j] = t;
                    }
                }
            }
        }

        // <Z_w> = sum_i st[i]^2 * (+1 if bit w of i is 0 else -1)
        float z[NQ] = {0.f, 0.f, 0.f, 0.f};
        #pragma unroll
        for (int i = 0; i < 16; ++i) {
            const float p = st[i] * st[i];
            #pragma unroll
            for (int w = 0; w < 4; ++w)
                z[w] += (i & (1 << w)) ? -p : p;
        }

        #pragma unroll
        for (int c = 0; c < NC; ++c) {
            float o = post_b[c];
            #pragma unroll
            for (int w = 0; w < NQ; ++w)
                o += z[w] * post_w[c * NQ + w];
            out[(size_t)row * NC + c] = o;
        }
    }
}

extern "C" void kernel_launch(void* const* d_in, const int* in_sizes, int n_in,
                              void* d_out, int out_size) {
    const float* x        = (const float*)d_in[0];
    const float* pre_w    = (const float*)d_in[1];
    const float* pre_b    = (const float*)d_in[2];
    const float* q_params = (const float*)d_in[3];
    const float* post_w   = (const float*)d_in[4];
    const float* post_b   = (const float*)d_in[5];
    float* out = (float*)d_out;

    qnet_fused_kernel<<<GRID, THREADS>>>(x, pre_w, pre_b, q_params,
                                         post_w, post_b, out);
}

// round 5
// speedup vs baseline: 1.2606x; 1.2606x over previous
#include <cuda_runtime.h>
#include <cuda_bf16.h>
#include <math.h>

// Problem constants (fixed by reference setup_inputs)
#define B_ROWS 16384
#define D_DIM  3072
#define NQ     4
#define NC     3

#define THREADS 256
#define WARPS_PER_BLOCK 8
#define ROWS_PER_WARP 4
#define ROWS_PER_BLOCK (WARPS_PER_BLOCK * ROWS_PER_WARP)   // 32
#define GRID (B_ROWS / ROWS_PER_BLOCK)                      // 512

// min 4 blocks/SM -> ptxas reg target <=64 -> 32 warps/SM and a single wave
// (592 concurrent-CTA slots >= 512 grid; at 3 CTAs/SM we had a 68-CTA tail wave).
__global__ __launch_bounds__(THREADS, 4)
void qnet_fused_kernel(const float* __restrict__ x,
                       const float* __restrict__ pre_w,
                       const float* __restrict__ pre_b,
                       const float* __restrict__ q_params,
                       const float* __restrict__ post_w,
                       const float* __restrict__ post_b,
                       float* __restrict__ out)
{
    // Stage pre_w [4][3072] in shared: 48 KB (4 CTAs x 49KB fits 228KB/SM).
    __shared__ float sw[NQ * D_DIM];
    {
        const float4* src = reinterpret_cast<const float4*>(pre_w);
        float4* dst = reinterpret_cast<float4*>(sw);
        #pragma unroll
        for (int i = threadIdx.x; i < NQ * D_DIM / 4; i += THREADS)
            dst[i] = src[i];
    }
    __syncthreads();

    const int warp = threadIdx.x >> 5;
    const int lane = threadIdx.x & 31;
    const int row0 = (blockIdx.x * WARPS_PER_BLOCK + warp) * ROWS_PER_WARP;

    const float4* xb = reinterpret_cast<const float4*>(x);
    const float4* xr0 = xb + (size_t)(row0 + 0) * (D_DIM / 4);
    const float4* xr1 = xb + (size_t)(row0 + 1) * (D_DIM / 4);
    const float4* xr2 = xb + (size_t)(row0 + 2) * (D_DIM / 4);
    const float4* xr3 = xb + (size_t)(row0 + 3) * (D_DIM / 4);
    const float4* sw4 = reinterpret_cast<const float4*>(sw);

    // acc[r][q] : partial dot of row (row0+r) with weight row q
    float acc[ROWS_PER_WARP][NQ];
    #pragma unroll
    for (int r = 0; r < ROWS_PER_WARP; ++r)
        #pragma unroll
        for (int q = 0; q < NQ; ++q) acc[r][q] = 0.0f;

    // Lanes sweep D in float4: per iter a warp covers 128 columns.
    // x is read exactly once -> stream it (.cs, evict-first) so it doesn't
    // fight the L2-resident weights.
    #pragma unroll 2
    for (int it = 0; it < D_DIM / 128; ++it) {
        const int c4 = it * 32 + lane;  // float4 column index

        float4 xv0 = __ldcs(xr0 + c4);
        float4 xv1 = __ldcs(xr1 + c4);
        float4 xv2 = __ldcs(xr2 + c4);
        float4 xv3 = __ldcs(xr3 + c4);

        float4 w0 = sw4[0 * (D_DIM / 4) + c4];
        float4 w1 = sw4[1 * (D_DIM / 4) + c4];
        float4 w2 = sw4[2 * (D_DIM / 4) + c4];
        float4 w3 = sw4[3 * (D_DIM / 4) + c4];

        acc[0][0] += xv0.x*w0.x + xv0.y*w0.y + xv0.z*w0.z + xv0.w*w0.w;
        acc[0][1] += xv0.x*w1.x + xv0.y*w1.y + xv0.z*w1.z + xv0.w*w1.w;
        acc[0][2] += xv0.x*w2.x + xv0.y*w2.y + xv0.z*w2.z + xv0.w*w2.w;
        acc[0][3] += xv0.x*w3.x + xv0.y*w3.y + xv0.z*w3.z + xv0.w*w3.w;
        acc[1][0] += xv1.x*w0.x + xv1.y*w0.y + xv1.z*w0.z + xv1.w*w0.w;
        acc[1][1] += xv1.x*w1.x + xv1.y*w1.y + xv1.z*w1.z + xv1.w*w1.w;
        acc[1][2] += xv1.x*w2.x + xv1.y*w2.y + xv1.z*w2.z + xv1.w*w2.w;
        acc[1][3] += xv1.x*w3.x + xv1.y*w3.y + xv1.z*w3.z + xv1.w*w3.w;
        acc[2][0] += xv2.x*w0.x + xv2.y*w0.y + xv2.z*w0.z + xv2.w*w0.w;
        acc[2][1] += xv2.x*w1.x + xv2.y*w1.y + xv2.z*w1.z + xv2.w*w1.w;
        acc[2][2] += xv2.x*w2.x + xv2.y*w2.y + xv2.z*w2.z + xv2.w*w2.w;
        acc[2][3] += xv2.x*w3.x + xv2.y*w3.y + xv2.z*w3.z + xv2.w*w3.w;
        acc[3][0] += xv3.x*w0.x + xv3.y*w0.y + xv3.z*w0.z + xv3.w*w0.w;
        acc[3][1] += xv3.x*w1.x + xv3.y*w1.y + xv3.z*w1.z + xv3.w*w1.w;
        acc[3][2] += xv3.x*w2.x + xv3.y*w2.y + xv3.z*w2.z + xv3.w*w2.w;
        acc[3][3] += xv3.x*w3.x + xv3.y*w3.y + xv3.z*w3.z + xv3.w*w3.w;
    }

    // Butterfly reduce each of the 16 accumulators across the warp.
    #pragma unroll
    for (int r = 0; r < ROWS_PER_WARP; ++r)
        #pragma unroll
        for (int q = 0; q < NQ; ++q) {
            float v = acc[r][q];
            v += __shfl_xor_sync(0xFFFFFFFFu, v, 16);
            v += __shfl_xor_sync(0xFFFFFFFFu, v, 8);
            v += __shfl_xor_sync(0xFFFFFFFFu, v, 4);
            v += __shfl_xor_sync(0xFFFFFFFFu, v, 2);
            v += __shfl_xor_sync(0xFFFFFFFFu, v, 1);
            acc[r][q] = v;
        }

    // Lanes 0..3 each handle one row: tanh encode -> 4-qubit real statevector
    // sim -> <Z_w> -> post linear. Register/local resident, fully unrolled.
    if (lane < ROWS_PER_WARP) {
        const int row = row0 + lane;

        // select acc[lane][*] with static indices (no dynamic reg indexing)
        float dot[NQ];
        #pragma unroll
        for (int q = 0; q < NQ; ++q) {
            float v = acc[0][q];
            if (lane == 1) v = acc[1][q];
            if (lane == 2) v = acc[2][q];
            if (lane == 3) v = acc[3][q];
            dot[q] = v;
        }

        const float PI_3 = 1.0471975511965976f;  // pi/3
        float cs[NQ], sn[NQ];
        #pragma unroll
        for (int q = 0; q < NQ; ++q) {
            float h = tanhf(dot[q] + pre_b[q]) * PI_3;
            sincosf(0.5f * h, &sn[q], &cs[q]);
        }

        // State after per-qubit RY encodings on |0>^4: real product state.
        float st[16];
        #pragma unroll
        for (int i = 0; i < 16; ++i) {
            float v = (i & 1) ? sn[0] : cs[0];
            v *= (i & 2) ? sn[1] : cs[1];
            v *= (i & 4) ? sn[2] : cs[2];
            v *= (i & 8) ? sn[3] : cs[3];
            st[i] = v;
        }

        // 3 layers: RY(q_params[8l+w]) on w=0..3, then CNOT(w,(w+1)%4) w=0..3
        #pragma unroll
        for (int l = 0; l < 3; ++l) {
            #pragma unroll
            for (int w = 0; w < 4; ++w) {
                const float th = q_params[l * 8 + w];
                float gs, gc;
                sincosf(0.5f * th, &gs, &gc);
                const int m = 1 << w;
                #pragma unroll
                for (int i = 0; i < 16; ++i) {
                    if (!(i & m)) {
                        const int j = i | m;
                        const float a0 = st[i], a1 = st[j];
                        st[i] = gc * a0 - gs * a1;
                        st[j] = gs * a0 + gc * a1;
                    }
                }
            }
            #pragma unroll
            for (int w = 0; w < 4; ++w) {
                const int cm = 1 << w;
                const int tm = 1 << ((w + 1) & 3);
                #pragma unroll
                for (int i = 0; i < 16; ++i) {
                    if ((i & cm) && !(i & tm)) {
                        const int j = i | tm;
                        const float t = st[i]; st[i] = st[j]; st[j] = t;
                    }
                }
            }
        }

        // <Z_w> = sum_i st[i]^2 * (+1 if bit w of i is 0 else -1)
        float z[NQ] = {0.f, 0.f, 0.f, 0.f};
        #pragma unroll
        for (int i = 0; i < 16; ++i) {
            const float p = st[i] * st[i];
            #pragma unroll
            for (int w = 0; w < 4; ++w)
                z[w] += (i & (1 << w)) ? -p : p;
        }

        #pragma unroll
        for (int c = 0; c < NC; ++c) {
            float o = post_b[c];
            #pragma unroll
            for (int w = 0; w < NQ; ++w)
                o += z[w] * post_w[c * NQ + w];
            out[(size_t)row * NC + c] = o;
        }
    }
}

extern "C" void kernel_launch(void* const* d_in, const int* in_sizes, int n_in,
                              void* d_out, int out_size) {
    const float* x        = (const float*)d_in[0];
    const float* pre_w    = (const float*)d_in[1];
    const float* pre_b    = (const float*)d_in[2];
    const float* q_params = (const float*)d_in[3];
    const float* post_w   = (const float*)d_in[4];
    const float* post_b   = (const float*)d_in[5];
    float* out = (float*)d_out;

    qnet_fused_kernel<<<GRID, THREADS>>>(x, pre_w, pre_b, q_params,
                                         post_w, post_b, out);
}